// round 7
// baseline (speedup 1.0000x reference)
#include <cuda_runtime.h>
#include <cuda_fp16.h>

#define HH 128
#define WW 128
#define PLANE (HH*WW)
#define CYC 21
#define TW 16
#define TH 16
#define HLW 26              // halo cols: tw0-5 .. tw0+20
#define HLH 21              // halo rows: th0 .. th0+20
#define NC (HLW*HLH)        // 546
#define NT 256              // 128 pixel-pairs x 2 jj-parity groups
#define NBLK 256            // 8*8*4

typedef unsigned long long u64;
typedef unsigned int u32;

__device__ float g_part[NBLK];
__device__ unsigned int g_cnt = 0;

__device__ __forceinline__ u64 pack2(float lo, float hi) {
    u64 r; asm("mov.b64 %0,{%1,%2};" : "=l"(r) : "f"(lo), "f"(hi)); return r;
}
__device__ __forceinline__ void unpack2(u64 v, float& lo, float& hi) {
    asm("mov.b64 {%0,%1},%2;" : "=f"(lo), "=f"(hi) : "l"(v));
}
__device__ __forceinline__ u64 add2(u64 a, u64 b) {
    u64 d; asm("add.rn.f32x2 %0,%1,%2;" : "=l"(d) : "l"(a), "l"(b)); return d;
}
__device__ __forceinline__ u64 mul2(u64 a, u64 b) {
    u64 d; asm("mul.rn.f32x2 %0,%1,%2;" : "=l"(d) : "l"(a), "l"(b)); return d;
}
__device__ __forceinline__ u64 ffma2(u64 a, u64 b, u64 c) {
    u64 d; asm("fma.rn.f32x2 %0,%1,%2,%3;" : "=l"(d) : "l"(a), "l"(b), "l"(c)); return d;
}
__device__ __forceinline__ float ex2(float v) {
    float r; asm("ex2.approx.ftz.f32 %0,%1;" : "=f"(r) : "f"(v)); return r;
}
__device__ __forceinline__ u32 hmul2u(u32 a, u32 b) {
    u32 d; asm("mul.rn.f16x2 %0,%1,%2;" : "=r"(d) : "r"(a), "r"(b)); return d;
}
__device__ __forceinline__ u32 hfma2u(u32 a, u32 b, u32 c) {
    u32 d; asm("fma.rn.f16x2 %0,%1,%2,%3;" : "=r"(d) : "r"(a), "r"(b), "r"(c)); return d;
}
__device__ __forceinline__ u32 splat16(float v) {
    u32 d; asm("cvt.rn.f16x2.f32 %0,%1,%1;" : "=r"(d) : "f"(v)); return d;
}

// fast 2^v for v <= 0 on fma/alu pipes (no MUFU). Max rel err ~4e-5.
__device__ __forceinline__ float fexp2n(float v) {
    v = fmaxf(v, -126.0f);
    const float MAGIC = 12582912.0f;        // 1.5 * 2^23
    float t = v + MAGIC;                    // integer(v) in low mantissa (RN)
    float fi = t - MAGIC;                   // round-to-nearest(v), exact
    float f = v - fi;                       // [-0.5, 0.5], exact (Sterbenz)
    int ei = __float_as_int(t) << 23;       // = round(v) << 23  (low 9 bits of 0x4B400000 are 0)
    float p = fmaf(f, 0.009618129f, 0.055504109f);
    p = fmaf(f, p, 0.240226507f);
    p = fmaf(f, p, 0.693147181f);
    p = fmaf(f, p, 1.0f);                   // 2^f
    return __int_as_float(__float_as_int(p) + ei);
}

#define XSCALE 8.493218003f               // sqrt(50 * log2(e)); |dx'|^2 = 50*log2e*|dx|^2
#define CXY   (-0.020037431123458f)       // -log2(e)/72
#define CEXP  (-72.13475204444817f)       // -50*log2(e)  (epilogue uses scaled x instead)

// column parity swizzle: even cols -> [0,13), odd cols -> [13,26)
__device__ __forceinline__ int swz(int c) { return (c & 1) * 13 + (c >> 1); }

__global__ __launch_bounds__(NT, 2) void crf_fused(const float* __restrict__ x,
                                                   const float* __restrict__ y,
                                                   float* __restrict__ out) {
    __shared__ float4 Ash4[NC];       // scaled (x0,x1,x2,0); OOB cells all-zero
    __shared__ uint4  ysh[3 * NC];    // y as fp16 half2 pairs, 24 ch (21 + pad)
    __shared__ float  TAB[78];        // [6][13]: 2*exy at [di][dj+6]; 0 outside half-window H
    __shared__ float  CS[6];          // CS[c] = sum_{k=1..c} exp(-k^2/72)
    __shared__ float  red[8];
    __shared__ int    lastflag;

    const int tid = threadIdx.x;
    const int g   = tid >> 7;         // jj parity group
    const int pid = tid & 127;
    const int px  = pid & 7;          // pair col: pixels (2px, 2px+1)
    const int py  = pid >> 3;         // pixel row 0..15
    const int th0 = blockIdx.y * TH, tw0 = blockIdx.x * TW;
    const int bz = blockIdx.z;
    const float* xb = x + (size_t)bz * 3 * PLANE;
    const float* yb = y + (size_t)bz * CYC * PLANE;

    // ---- tables ----
    for (int t = tid; t < 78; t += NT) {
        int di = t / 13, dj = t % 13 - 6;
        float v = 0.0f;
        if (dj >= -5 && dj <= 5 && (di >= 1 || dj >= 1))
            v = 2.0f * __expf(-(float)(di * di + dj * dj) * (1.0f / 72.0f));
        TAB[t] = v;
    }
    if (tid < 6) {
        float s = 0.0f;
        for (int k = 1; k <= tid; ++k) s += __expf(-(float)(k * k) * (1.0f / 72.0f));
        CS[tid] = s;    // CS[0] = 0
    }

    // ---- halo load: x scaled fp32, y fp16-packed; OOB cells zero ----
    for (int cell = tid; cell < NC; cell += NT) {
        int r = cell / HLW, c = cell - r * HLW;
        int gh = th0 + r, gw = tw0 - 5 + c;
        bool v = (gh < HH) && ((unsigned)gw < WW);
        int gidx = gh * WW + gw;
        int dst = r * HLW + swz(c);
        float4 a = make_float4(0.f, 0.f, 0.f, 0.f);
        if (v) {
            a.x = xb[gidx] * XSCALE;
            a.y = xb[PLANE + gidx] * XSCALE;
            a.z = xb[2 * PLANE + gidx] * XSCALE;
        }
        Ash4[dst] = a;
        #pragma unroll
        for (int cg = 0; cg < 3; ++cg) {
            uint4 q = make_uint4(0u, 0u, 0u, 0u);
            if (v) {
                u32 h[4];
                #pragma unroll
                for (int pq = 0; pq < 4; ++pq) {
                    int ch = cg * 8 + pq * 2;
                    float a0 = (ch < CYC) ? yb[ch * PLANE + gidx] : 0.f;
                    float a1 = (ch + 1 < CYC) ? yb[(ch + 1) * PLANE + gidx] : 0.f;
                    __half2 hh = __floats2half2_rn(a0, a1);
                    h[pq] = *(u32*)&hh;
                }
                q.x = h[0]; q.y = h[1]; q.z = h[2]; q.w = h[3];
            }
            ysh[cg * NC + dst] = q;
        }
    }
    __syncthreads();

    // ---- per-thread: pixel pair (py, 2px) & (py, 2px+1) ----
    const int cc0 = py * HLW + swz(2 * px + 5);
    const int cc1 = py * HLW + swz(2 * px + 6);
    u32 yc0[12], yc1[12];
    {
        uint4 a0 = ysh[cc0], b0 = ysh[NC + cc0], c0 = ysh[2 * NC + cc0];
        yc0[0]=a0.x; yc0[1]=a0.y; yc0[2]=a0.z; yc0[3]=a0.w;
        yc0[4]=b0.x; yc0[5]=b0.y; yc0[6]=b0.z; yc0[7]=b0.w;
        yc0[8]=c0.x; yc0[9]=c0.y; yc0[10]=c0.z; yc0[11]=c0.w;
        uint4 a1 = ysh[cc1], b1 = ysh[NC + cc1], c1 = ysh[2 * NC + cc1];
        yc1[0]=a1.x; yc1[1]=a1.y; yc1[2]=a1.z; yc1[3]=a1.w;
        yc1[4]=b1.x; yc1[5]=b1.y; yc1[6]=b1.z; yc1[7]=b1.w;
        yc1[8]=c1.x; yc1[9]=c1.y; yc1[10]=c1.z; yc1[11]=c1.w;
    }
    const float4 xc0 = Ash4[cc0];
    const float4 xc1 = Ash4[cc1];
    const u64 ng0 = pack2(-xc0.x, -xc1.x);
    const u64 ng1 = pack2(-xc0.y, -xc1.y);
    const u64 ng2 = pack2(-xc0.z, -xc1.z);

    u32 accP0 = 0u, accP1 = 0u;   // half2 accumulators of K*dot
    float acc1 = 0.0f;
    const float* tg = TAB + g;

    // ---- mainloop: 6 rows (di=0..5) x 6 cols (this group's jj parity), mask-free ----
    #pragma unroll
    for (int ii = 0; ii < 6; ++ii) {
        const int rb = (py + ii) * HLW + g * 13 + px;
        const float* t = tg + ii * 13;
        #pragma unroll
        for (int m = 0; m < 6; ++m) {
            const int cell = rb + m;
            const float4 xv = Ash4[cell];
            const uint4 v0 = ysh[cell];
            const uint4 v1 = ysh[NC + cell];
            const uint4 v2 = ysh[2 * NC + cell];

            // scaled image-diff: sp = 50*log2e*|x_q - x_p|^2, packed over (pc0,pc1)
            u64 d0 = add2(pack2(xv.x, xv.x), ng0);
            u64 d1 = add2(pack2(xv.y, xv.y), ng1);
            u64 d2 = add2(pack2(xv.z, xv.z), ng2);
            u64 sp = mul2(d0, d0); sp = ffma2(d1, d1, sp); sp = ffma2(d2, d2, sp);
            float s0, s1; unpack2(sp, s0, s1);
            const float F0 = fmaf(0.9f, fexp2n(-s0), 0.1f);
            const float F1 = fmaf(0.9f, fexp2n(-s1), 0.1f);
            const float K0 = F0 * t[2 * m + 1];
            const float K1 = F1 * t[2 * m];
            acc1 += K0 + K1;

            // dots <y_c, y_q> in fp16x2 (two independent 12-deep chains)
            u32 dp0 = hmul2u(v0.x, yc0[0]);
            u32 dp1 = hmul2u(v0.x, yc1[0]);
            dp0 = hfma2u(v0.y, yc0[1], dp0);  dp1 = hfma2u(v0.y, yc1[1], dp1);
            dp0 = hfma2u(v0.z, yc0[2], dp0);  dp1 = hfma2u(v0.z, yc1[2], dp1);
            dp0 = hfma2u(v0.w, yc0[3], dp0);  dp1 = hfma2u(v0.w, yc1[3], dp1);
            dp0 = hfma2u(v1.x, yc0[4], dp0);  dp1 = hfma2u(v1.x, yc1[4], dp1);
            dp0 = hfma2u(v1.y, yc0[5], dp0);  dp1 = hfma2u(v1.y, yc1[5], dp1);
            dp0 = hfma2u(v1.z, yc0[6], dp0);  dp1 = hfma2u(v1.z, yc1[6], dp1);
            dp0 = hfma2u(v1.w, yc0[7], dp0);  dp1 = hfma2u(v1.w, yc1[7], dp1);
            dp0 = hfma2u(v2.x, yc0[8], dp0);  dp1 = hfma2u(v2.x, yc1[8], dp1);
            dp0 = hfma2u(v2.y, yc0[9], dp0);  dp1 = hfma2u(v2.y, yc1[9], dp1);
            dp0 = hfma2u(v2.z, yc0[10], dp0); dp1 = hfma2u(v2.z, yc1[10], dp1);
            dp0 = hfma2u(v2.w, yc0[11], dp0); dp1 = hfma2u(v2.w, yc1[11], dp1);

            accP0 = hfma2u(splat16(K0), dp0, accP0);
            accP1 = hfma2u(splat16(K1), dp1, accP1);
        }
    }

    // ---- epilogue ----
    float acc2;
    {
        __half2 a = *(__half2*)&accP0;
        __half2 b = *(__half2*)&accP1;
        acc2 = (__low2float(a) + __high2float(a)) + (__low2float(b) + __high2float(b));
    }
    if (g == 0) {
        // per-pixel corrections: subtract mask-free junk, add true OOB (full window, unhalved)
        const float CS5 = CS[5];
        const float SHt = CS5 * (1.0f + 2.0f * CS5) + CS5;
        const int h = th0 + py;
        const float csr = CS[min(5, 127 - h)];
        const int rv = min(5, 127 - h) + min(5, h) + 1;
        #pragma unroll
        for (int pc = 0; pc < 2; ++pc) {
            const int w = tw0 + 2 * px + pc;
            const float csw1 = CS[min(5, w)];
            const float csw2 = CS[min(5, 127 - w)];
            const float SHv = csr * (1.0f + csw1 + csw2) + csw2;
            const int cv = min(5, 127 - w) + min(5, w) + 1;
            const int noob = 121 - rv * cv;
            const float4 xc = pc ? xc1 : xc0;
            const float sxs = xc.x * xc.x + xc.y * xc.y + xc.z * xc.z;   // already scaled
            const float F = fmaf(0.9f, ex2(-sxs), 0.1f);
            acc1 += (float)noob * ex2((float)(h * h + w * w) * CXY) * F
                  - F * 2.0f * (SHt - SHv);
        }
    }

    // ---- block reduction + fused final reduction (deterministic) ----
    float part = acc1 - acc2;
    #pragma unroll
    for (int o = 16; o > 0; o >>= 1) part += __shfl_xor_sync(0xffffffffu, part, o);
    const int warp = tid >> 5, lane = tid & 31;
    if (lane == 0) red[warp] = part;
    __syncthreads();
    const int bid = ((bz * gridDim.y) + blockIdx.y) * gridDim.x + blockIdx.x;
    if (tid == 0) {
        float s = 0.f;
        #pragma unroll
        for (int wi = 0; wi < 8; ++wi) s += red[wi];
        g_part[bid] = s;
        __threadfence();
        unsigned old = atomicAdd(&g_cnt, 1u);
        lastflag = (old == NBLK - 1) ? 1 : 0;
    }
    __syncthreads();
    if (lastflag) {
        float v = g_part[tid];     // NBLK == NT == 256
        #pragma unroll
        for (int o = 16; o > 0; o >>= 1) v += __shfl_xor_sync(0xffffffffu, v, o);
        if (lane == 0) red[warp] = v;
        __syncthreads();
        if (tid == 0) {
            float s = 0.f;
            #pragma unroll
            for (int wi = 0; wi < 8; ++wi) s += red[wi];
            out[0] = s * (1.0f / 65536.0f);
            g_cnt = 0;
        }
    }
}

extern "C" void kernel_launch(void* const* d_in, const int* in_sizes, int n_in,
                              void* d_out, int out_size) {
    const float* x = (const float*)d_in[0];
    const float* y = (const float*)d_in[1];
    (void)in_sizes; (void)n_in; (void)out_size;
    dim3 grid(WW / TW, HH / TH, 4);
    crf_fused<<<grid, NT>>>(x, y, (float*)d_out);
}

// round 8
// speedup vs baseline: 1.0152x; 1.0152x over previous
#include <cuda_runtime.h>
#include <cuda_fp16.h>

#define HH 128
#define WW 128
#define PLANE (HH*WW)
#define CYC 21
#define TW 16
#define TH 8
#define HLW 26              // halo cols: tw0-5 .. tw0+20
#define HLH 13              // halo rows: th0 .. th0+12
#define NC (HLW*HLH)        // 338
#define NT 128              // 64 pixel-pairs x 2 jj-parity groups
#define NBLK 512            // 8*16*4

typedef unsigned long long u64;
typedef unsigned int u32;

__device__ float g_part[NBLK];
__device__ unsigned int g_cnt = 0;

__device__ __forceinline__ u64 pack2(float lo, float hi) {
    u64 r; asm("mov.b64 %0,{%1,%2};" : "=l"(r) : "f"(lo), "f"(hi)); return r;
}
__device__ __forceinline__ void unpack2(u64 v, float& lo, float& hi) {
    asm("mov.b64 {%0,%1},%2;" : "=f"(lo), "=f"(hi) : "l"(v));
}
__device__ __forceinline__ u64 add2(u64 a, u64 b) {
    u64 d; asm("add.rn.f32x2 %0,%1,%2;" : "=l"(d) : "l"(a), "l"(b)); return d;
}
__device__ __forceinline__ u64 mul2(u64 a, u64 b) {
    u64 d; asm("mul.rn.f32x2 %0,%1,%2;" : "=l"(d) : "l"(a), "l"(b)); return d;
}
__device__ __forceinline__ u64 ffma2(u64 a, u64 b, u64 c) {
    u64 d; asm("fma.rn.f32x2 %0,%1,%2,%3;" : "=l"(d) : "l"(a), "l"(b), "l"(c)); return d;
}
__device__ __forceinline__ float ex2(float v) {
    float r; asm("ex2.approx.ftz.f32 %0,%1;" : "=f"(r) : "f"(v)); return r;
}
__device__ __forceinline__ u32 hmul2u(u32 a, u32 b) {
    u32 d; asm("mul.rn.f16x2 %0,%1,%2;" : "=r"(d) : "r"(a), "r"(b)); return d;
}
__device__ __forceinline__ u32 hfma2u(u32 a, u32 b, u32 c) {
    u32 d; asm("fma.rn.f16x2 %0,%1,%2,%3;" : "=r"(d) : "r"(a), "r"(b), "r"(c)); return d;
}
__device__ __forceinline__ u32 hadd2u(u32 a, u32 b) {
    u32 d; asm("add.rn.f16x2 %0,%1,%2;" : "=r"(d) : "r"(a), "r"(b)); return d;
}
__device__ __forceinline__ u32 splat16(float v) {
    u32 d; asm("cvt.rn.f16x2.f32 %0,%1,%1;" : "=r"(d) : "f"(v)); return d;
}

#define XSCALE 8.493218003f               // sqrt(50*log2(e)); makes sp = 50*log2e*|dx|^2
#define CXY   (-0.020037431123458f)       // -log2(e)/72

// column parity swizzle: even cols -> [0,13), odd cols -> [13,26)
__device__ __forceinline__ int swz(int c) { return (c & 1) * 13 + (c >> 1); }

__global__ __launch_bounds__(NT, 6) void crf_fused(const float* __restrict__ x,
                                                   const float* __restrict__ y,
                                                   float* __restrict__ out) {
    __shared__ float4 Ash4[NC];       // scaled (x0,x1,x2,0); OOB cells all-zero
    __shared__ uint4  ysh[3 * NC];    // y as fp16 half2 pairs, 24 ch (21 + pad)
    __shared__ float  TAB[78];        // [6][13]: 2*exy at [di][dj+6]; 0 outside half-window H
    __shared__ float  CS[6];          // CS[c] = sum_{k=1..c} exp(-k^2/72)
    __shared__ float  red[4];
    __shared__ int    lastflag;

    const int tid = threadIdx.x;
    const int g   = tid >> 6;         // jj parity group
    const int pid = tid & 63;
    const int px  = pid & 7;          // pair col: pixels (2px, 2px+1)
    const int py  = pid >> 3;         // pixel row 0..7
    const int th0 = blockIdx.y * TH, tw0 = blockIdx.x * TW;
    const int bz = blockIdx.z;
    const float* xb = x + (size_t)bz * 3 * PLANE;
    const float* yb = y + (size_t)bz * CYC * PLANE;

    // ---- tables ----
    for (int t = tid; t < 78; t += NT) {
        int di = t / 13, dj = t % 13 - 6;
        float v = 0.0f;
        if (dj >= -5 && dj <= 5 && (di >= 1 || dj >= 1))
            v = 2.0f * __expf(-(float)(di * di + dj * dj) * (1.0f / 72.0f));
        TAB[t] = v;
    }
    if (tid < 6) {
        float s = 0.0f;
        for (int k = 1; k <= tid; ++k) s += __expf(-(float)(k * k) * (1.0f / 72.0f));
        CS[tid] = s;    // CS[0] = 0
    }

    // ---- halo load: x scaled fp32, y fp16-packed; OOB cells zero ----
    for (int cell = tid; cell < NC; cell += NT) {
        int r = cell / HLW, c = cell - r * HLW;
        int gh = th0 + r, gw = tw0 - 5 + c;
        bool v = (gh < HH) && ((unsigned)gw < WW);
        int gidx = gh * WW + gw;
        int dst = r * HLW + swz(c);
        float4 a = make_float4(0.f, 0.f, 0.f, 0.f);
        if (v) {
            a.x = xb[gidx] * XSCALE;
            a.y = xb[PLANE + gidx] * XSCALE;
            a.z = xb[2 * PLANE + gidx] * XSCALE;
        }
        Ash4[dst] = a;
        #pragma unroll
        for (int cg = 0; cg < 3; ++cg) {
            uint4 q = make_uint4(0u, 0u, 0u, 0u);
            if (v) {
                u32 h[4];
                #pragma unroll
                for (int pq = 0; pq < 4; ++pq) {
                    int ch = cg * 8 + pq * 2;
                    float a0 = (ch < CYC) ? yb[ch * PLANE + gidx] : 0.f;
                    float a1 = (ch + 1 < CYC) ? yb[(ch + 1) * PLANE + gidx] : 0.f;
                    __half2 hh = __floats2half2_rn(a0, a1);
                    h[pq] = *(u32*)&hh;
                }
                q.x = h[0]; q.y = h[1]; q.z = h[2]; q.w = h[3];
            }
            ysh[cg * NC + dst] = q;
        }
    }
    __syncthreads();

    // ---- per-thread: pixel pair (py, 2px) & (py, 2px+1) ----
    const int cc0 = py * HLW + swz(2 * px + 5);
    const int cc1 = py * HLW + swz(2 * px + 6);
    u32 yc0[12], yc1[12];
    {
        uint4 a0 = ysh[cc0], b0 = ysh[NC + cc0], c0 = ysh[2 * NC + cc0];
        yc0[0]=a0.x; yc0[1]=a0.y; yc0[2]=a0.z; yc0[3]=a0.w;
        yc0[4]=b0.x; yc0[5]=b0.y; yc0[6]=b0.z; yc0[7]=b0.w;
        yc0[8]=c0.x; yc0[9]=c0.y; yc0[10]=c0.z; yc0[11]=c0.w;
        uint4 a1 = ysh[cc1], b1 = ysh[NC + cc1], c1 = ysh[2 * NC + cc1];
        yc1[0]=a1.x; yc1[1]=a1.y; yc1[2]=a1.z; yc1[3]=a1.w;
        yc1[4]=b1.x; yc1[5]=b1.y; yc1[6]=b1.z; yc1[7]=b1.w;
        yc1[8]=c1.x; yc1[9]=c1.y; yc1[10]=c1.z; yc1[11]=c1.w;
    }
    const float4 xc0 = Ash4[cc0];
    const float4 xc1 = Ash4[cc1];
    const u64 ng0 = pack2(-xc0.x, -xc1.x);
    const u64 ng1 = pack2(-xc0.y, -xc1.y);
    const u64 ng2 = pack2(-xc0.z, -xc1.z);

    u32 accP0 = 0u, accP1 = 0u;   // half2 accumulators of K*dot
    float acc1 = 0.0f;
    const float* tg = TAB + g;

    // ---- mainloop: 6 rows (di=0..5) x 6 cols (this group's jj parity), mask-free ----
    #pragma unroll
    for (int ii = 0; ii < 6; ++ii) {
        const int rb = (py + ii) * HLW + g * 13 + px;
        const float* t = tg + ii * 13;
        #pragma unroll
        for (int m = 0; m < 6; ++m) {
            const int cell = rb + m;
            const float4 xv = Ash4[cell];
            const uint4 v0 = ysh[cell];
            const uint4 v1 = ysh[NC + cell];
            const uint4 v2 = ysh[2 * NC + cell];

            // scaled image-diff: sp = 50*log2e*|x_q - x_p|^2, packed over (pc0,pc1)
            u64 d0 = add2(pack2(xv.x, xv.x), ng0);
            u64 d1 = add2(pack2(xv.y, xv.y), ng1);
            u64 d2 = add2(pack2(xv.z, xv.z), ng2);
            u64 sp = mul2(d0, d0); sp = ffma2(d1, d1, sp); sp = ffma2(d2, d2, sp);
            float s0, s1; unpack2(sp, s0, s1);
            const float F0 = fmaf(0.9f, ex2(-s0), 0.1f);
            const float F1 = fmaf(0.9f, ex2(-s1), 0.1f);
            const float K0 = F0 * t[2 * m + 1];
            const float K1 = F1 * t[2 * m];
            acc1 += K0 + K1;

            // dots <y_c, y_q> in fp16x2: 4 independent 6-deep chains
            u32 dp0a = hmul2u(v0.x, yc0[0]);
            u32 dp1a = hmul2u(v0.x, yc1[0]);
            u32 dp0b = hmul2u(v1.z, yc0[6]);
            u32 dp1b = hmul2u(v1.z, yc1[6]);
            dp0a = hfma2u(v0.y, yc0[1], dp0a);  dp1a = hfma2u(v0.y, yc1[1], dp1a);
            dp0b = hfma2u(v1.w, yc0[7], dp0b);  dp1b = hfma2u(v1.w, yc1[7], dp1b);
            dp0a = hfma2u(v0.z, yc0[2], dp0a);  dp1a = hfma2u(v0.z, yc1[2], dp1a);
            dp0b = hfma2u(v2.x, yc0[8], dp0b);  dp1b = hfma2u(v2.x, yc1[8], dp1b);
            dp0a = hfma2u(v0.w, yc0[3], dp0a);  dp1a = hfma2u(v0.w, yc1[3], dp1a);
            dp0b = hfma2u(v2.y, yc0[9], dp0b);  dp1b = hfma2u(v2.y, yc1[9], dp1b);
            dp0a = hfma2u(v1.x, yc0[4], dp0a);  dp1a = hfma2u(v1.x, yc1[4], dp1a);
            dp0b = hfma2u(v2.z, yc0[10], dp0b); dp1b = hfma2u(v2.z, yc1[10], dp1b);
            dp0a = hfma2u(v1.y, yc0[5], dp0a);  dp1a = hfma2u(v1.y, yc1[5], dp1a);
            dp0b = hfma2u(v2.w, yc0[11], dp0b); dp1b = hfma2u(v2.w, yc1[11], dp1b);
            const u32 dp0 = hadd2u(dp0a, dp0b);
            const u32 dp1 = hadd2u(dp1a, dp1b);

            accP0 = hfma2u(splat16(K0), dp0, accP0);
            accP1 = hfma2u(splat16(K1), dp1, accP1);
        }
    }

    // ---- epilogue ----
    float acc2;
    {
        __half2 a = *(__half2*)&accP0;
        __half2 b = *(__half2*)&accP1;
        acc2 = (__low2float(a) + __high2float(a)) + (__low2float(b) + __high2float(b));
    }
    if (g == 0) {
        // per-pixel corrections: subtract mask-free junk, add true OOB (full window, unhalved)
        const float CS5 = CS[5];
        const float SHt = CS5 * (1.0f + 2.0f * CS5) + CS5;
        const int h = th0 + py;
        const float csr = CS[min(5, 127 - h)];
        const int rv = min(5, 127 - h) + min(5, h) + 1;
        #pragma unroll
        for (int pc = 0; pc < 2; ++pc) {
            const int w = tw0 + 2 * px + pc;
            const float csw1 = CS[min(5, w)];
            const float csw2 = CS[min(5, 127 - w)];
            const float SHv = csr * (1.0f + csw1 + csw2) + csw2;
            const int cv = min(5, 127 - w) + min(5, w) + 1;
            const int noob = 121 - rv * cv;
            const float4 xc = pc ? xc1 : xc0;
            const float sxs = xc.x * xc.x + xc.y * xc.y + xc.z * xc.z;   // already scaled
            const float F = fmaf(0.9f, ex2(-sxs), 0.1f);
            acc1 += (float)noob * ex2((float)(h * h + w * w) * CXY) * F
                  - F * 2.0f * (SHt - SHv);
        }
    }

    // ---- block reduction + fused final reduction (deterministic) ----
    float part = acc1 - acc2;
    #pragma unroll
    for (int o = 16; o > 0; o >>= 1) part += __shfl_xor_sync(0xffffffffu, part, o);
    const int warp = tid >> 5, lane = tid & 31;
    if (lane == 0) red[warp] = part;
    __syncthreads();
    const int bid = ((bz * gridDim.y) + blockIdx.y) * gridDim.x + blockIdx.x;
    if (tid == 0) {
        g_part[bid] = (red[0] + red[1]) + (red[2] + red[3]);
        __threadfence();
        unsigned old = atomicAdd(&g_cnt, 1u);
        lastflag = (old == NBLK - 1) ? 1 : 0;
    }
    __syncthreads();
    if (lastflag) {
        float v = (g_part[tid] + g_part[tid + 128]) +
                  (g_part[tid + 256] + g_part[tid + 384]);
        #pragma unroll
        for (int o = 16; o > 0; o >>= 1) v += __shfl_xor_sync(0xffffffffu, v, o);
        if (lane == 0) red[warp] = v;
        __syncthreads();
        if (tid == 0) {
            out[0] = ((red[0] + red[1]) + (red[2] + red[3])) * (1.0f / 65536.0f);
            g_cnt = 0;
        }
    }
}

extern "C" void kernel_launch(void* const* d_in, const int* in_sizes, int n_in,
                              void* d_out, int out_size) {
    const float* x = (const float*)d_in[0];
    const float* y = (const float*)d_in[1];
    (void)in_sizes; (void)n_in; (void)out_size;
    dim3 grid(WW / TW, HH / TH, 4);
    crf_fused<<<grid, NT>>>(x, y, (float*)d_out);
}

// round 9
// speedup vs baseline: 1.1555x; 1.1382x over previous
#include <cuda_runtime.h>
#include <cuda_fp16.h>

#define HH 128
#define WW 128
#define PLANE (HH*WW)
#define CYC 21
#define TW 16
#define TH 8
#define HLW 26              // halo cols: tw0-5 .. tw0+20
#define HLH 13              // halo rows: th0 .. th0+12
#define NC (HLW*HLH)        // 338
#define NT 128              // 64 pixel-pairs x 2 jj-parity groups
#define NBLK 512            // 8*16*4

typedef unsigned long long u64;
typedef unsigned int u32;

__device__ float g_part[NBLK];
__device__ unsigned int g_cnt = 0;

__device__ __forceinline__ u64 pack2(float lo, float hi) {
    u64 r; asm("mov.b64 %0,{%1,%2};" : "=l"(r) : "f"(lo), "f"(hi)); return r;
}
__device__ __forceinline__ void unpack2(u64 v, float& lo, float& hi) {
    asm("mov.b64 {%0,%1},%2;" : "=f"(lo), "=f"(hi) : "l"(v));
}
__device__ __forceinline__ u64 add2(u64 a, u64 b) {
    u64 d; asm("add.rn.f32x2 %0,%1,%2;" : "=l"(d) : "l"(a), "l"(b)); return d;
}
__device__ __forceinline__ u64 mul2(u64 a, u64 b) {
    u64 d; asm("mul.rn.f32x2 %0,%1,%2;" : "=l"(d) : "l"(a), "l"(b)); return d;
}
__device__ __forceinline__ u64 ffma2(u64 a, u64 b, u64 c) {
    u64 d; asm("fma.rn.f32x2 %0,%1,%2,%3;" : "=l"(d) : "l"(a), "l"(b), "l"(c)); return d;
}
__device__ __forceinline__ float ex2(float v) {
    float r; asm("ex2.approx.ftz.f32 %0,%1;" : "=f"(r) : "f"(v)); return r;
}
__device__ __forceinline__ u32 hmul2u(u32 a, u32 b) {
    u32 d; asm("mul.rn.f16x2 %0,%1,%2;" : "=r"(d) : "r"(a), "r"(b)); return d;
}
__device__ __forceinline__ u32 hfma2u(u32 a, u32 b, u32 c) {
    u32 d; asm("fma.rn.f16x2 %0,%1,%2,%3;" : "=r"(d) : "r"(a), "r"(b), "r"(c)); return d;
}
__device__ __forceinline__ u32 hadd2u(u32 a, u32 b) {
    u32 d; asm("add.rn.f16x2 %0,%1,%2;" : "=r"(d) : "r"(a), "r"(b)); return d;
}
__device__ __forceinline__ u32 prmt(u32 a, u32 sel) {
    u32 d; asm("prmt.b32 %0,%1,%1,%2;" : "=r"(d) : "r"(a), "r"(sel)); return d;
}

#define XSCALE 8.493218003f               // sqrt(50*log2(e)); sp = 50*log2e*|dx|^2
#define CXY   (-0.020037431123458f)       // -log2(e)/72

// half-window exy value: 2*exp(-(di^2+dj^2)/72) inside H, else 0
__device__ __forceinline__ float hw_exy(int di, int dj) {
    if (dj >= -5 && dj <= 5 && (di >= 1 || dj >= 1))
        return 2.0f * __expf(-(float)(di * di + dj * dj) * (1.0f / 72.0f));
    return 0.0f;
}

// column parity swizzle: even cols -> [0,13), odd cols -> [13,26)
__device__ __forceinline__ int swz(int c) { return (c & 1) * 13 + (c >> 1); }

__global__ __launch_bounds__(NT, 4) void crf_fused(const float* __restrict__ x,
                                                   const float* __restrict__ y,
                                                   float* __restrict__ out) {
    __shared__ float4 Ash4[NC];       // scaled (x0,x1,x2,0); OOB cells all-zero
    __shared__ uint4  ysh[3 * NC];    // y fp16 half2 pairs; ch21 slot = in-bounds flag (1.0)
    __shared__ float4 TABP[2 * 36];   // per (g, ii*6+m): (0.9*t_pc0, 0.9*t_pc1, 0.1*t_pc0, 0.1*t_pc1)
    __shared__ float  red[4];
    __shared__ int    lastflag;

    const int tid = threadIdx.x;
    const int g   = tid >> 6;         // jj parity group
    const int pid = tid & 63;
    const int px  = pid & 7;          // pair col: pixels (2px, 2px+1)
    const int py  = pid >> 3;         // pixel row 0..7
    const int th0 = blockIdx.y * TH, tw0 = blockIdx.x * TW;
    const int bz = blockIdx.z;
    const float* xb = x + (size_t)bz * 3 * PLANE;
    const float* yb = y + (size_t)bz * CYC * PLANE;

    // ---- folded K table: t = TAB[ii*13 + g + 2m (+1)] with dj = col-6 ----
    for (int t = tid; t < 72; t += NT) {
        int g2 = t / 36, idx = t - g2 * 36;
        int ii = idx / 6, m = idx - ii * 6;
        float t0 = hw_exy(ii, g2 + 2 * m + 1 - 6);   // pc0 multiplier
        float t1 = hw_exy(ii, g2 + 2 * m - 6);       // pc1 multiplier
        TABP[g2 * 36 + idx] = make_float4(0.9f * t0, 0.9f * t1, 0.1f * t0, 0.1f * t1);
    }

    // ---- halo load: x scaled fp32; y fp16-packed with flag channel; OOB zero ----
    for (int cell = tid; cell < NC; cell += NT) {
        int r = cell / HLW, c = cell - r * HLW;
        int gh = th0 + r, gw = tw0 - 5 + c;
        bool v = (gh < HH) && ((unsigned)gw < WW);
        int gidx = gh * WW + gw;
        int dst = r * HLW + swz(c);
        float4 a = make_float4(0.f, 0.f, 0.f, 0.f);
        if (v) {
            a.x = xb[gidx] * XSCALE;
            a.y = xb[PLANE + gidx] * XSCALE;
            a.z = xb[2 * PLANE + gidx] * XSCALE;
        }
        Ash4[dst] = a;
        #pragma unroll
        for (int cg = 0; cg < 3; ++cg) {
            uint4 q = make_uint4(0u, 0u, 0u, 0u);
            if (v) {
                u32 h[4];
                #pragma unroll
                for (int pq = 0; pq < 4; ++pq) {
                    int ch = cg * 8 + pq * 2;
                    float a0 = (ch < CYC) ? yb[ch * PLANE + gidx] : 0.f;
                    float a1 = (ch + 1 < CYC) ? yb[(ch + 1) * PLANE + gidx]
                                              : ((ch + 1 == CYC) ? 1.0f : 0.f);  // flag in ch21
                    __half2 hh = __floats2half2_rn(a0, a1);
                    h[pq] = *(u32*)&hh;
                }
                q.x = h[0]; q.y = h[1]; q.z = h[2]; q.w = h[3];
            }
            ysh[cg * NC + dst] = q;
        }
    }
    __syncthreads();

    // ---- per-thread centers ----
    const int cc0 = py * HLW + swz(2 * px + 5);
    const int cc1 = py * HLW + swz(2 * px + 6);
    u32 yc0[11], yc1[11];
    {
        uint4 a0 = ysh[cc0], b0 = ysh[NC + cc0], c0 = ysh[2 * NC + cc0];
        yc0[0]=a0.x; yc0[1]=a0.y; yc0[2]=a0.z; yc0[3]=a0.w;
        yc0[4]=b0.x; yc0[5]=b0.y; yc0[6]=b0.z; yc0[7]=b0.w;
        yc0[8]=c0.x; yc0[9]=c0.y; yc0[10]=c0.z;
        uint4 a1 = ysh[cc1], b1 = ysh[NC + cc1], c1 = ysh[2 * NC + cc1];
        yc1[0]=a1.x; yc1[1]=a1.y; yc1[2]=a1.z; yc1[3]=a1.w;
        yc1[4]=b1.x; yc1[5]=b1.y; yc1[6]=b1.z; yc1[7]=b1.w;
        yc1[8]=c1.x; yc1[9]=c1.y; yc1[10]=c1.z;
    }
    // overwrite the center's ch21 flag with -1.0 (half 0xBC00): dot' = <y,y> - 1
    yc0[10] = (yc0[10] & 0x0000FFFFu) | 0xBC000000u;
    yc1[10] = (yc1[10] & 0x0000FFFFu) | 0xBC000000u;

    const float4 xc0 = Ash4[cc0];
    const float4 xc1 = Ash4[cc1];
    const u64 ng0 = pack2(-xc0.x, -xc1.x);
    const u64 ng1 = pack2(-xc0.y, -xc1.y);
    const u64 ng2 = pack2(-xc0.z, -xc1.z);
    const u64 cm1 = pack2(-1.0f, -1.0f);

    u32 accP0 = 0u, accP1 = 0u;       // half2 accumulators of K*dot'
    const float4* tabg = TABP + g * 36;
    const int rbase = py * HLW + g * 13 + px;

    // ---- software-pipelined mainloop over 36 cells ----
    float4 xv  = Ash4[rbase];
    uint4  v0  = ysh[rbase];
    uint4  v1  = ysh[NC + rbase];
    uint4  v2  = ysh[2 * NC + rbase];
    float4 tp  = tabg[0];

    #pragma unroll
    for (int idx = 0; idx < 36; ++idx) {
        const float4 cxv = xv;
        const uint4 cv0 = v0, cv1 = v1, cv2 = v2;
        const float4 ctp = tp;
        if (idx < 35) {
            const int ni = idx + 1;
            const int ncell = rbase + (ni / 6) * HLW + (ni % 6);
            xv = Ash4[ncell];
            v0 = ysh[ncell];
            v1 = ysh[NC + ncell];
            v2 = ysh[2 * NC + ncell];
            tp = tabg[ni];
        }

        // scaled image-diff: sp = 50*log2e*|x_q - x_p|^2, packed over (pc0,pc1)
        u64 d0 = add2(pack2(cxv.x, cxv.x), ng0);
        u64 d1 = add2(pack2(cxv.y, cxv.y), ng1);
        u64 d2 = add2(pack2(cxv.z, cxv.z), ng2);
        u64 sp = mul2(d0, d0); sp = ffma2(d1, d1, sp); sp = ffma2(d2, d2, sp);
        sp = mul2(sp, cm1);
        float ns0, ns1; unpack2(sp, ns0, ns1);
        const float E0 = ex2(ns0), E1 = ex2(ns1);
        const float K0 = fmaf(E0, ctp.x, ctp.z);
        const float K1 = fmaf(E1, ctp.y, ctp.w);
        __half2 kh = __floats2half2_rn(K0, K1);
        const u32 Kp = *(u32*)&kh;
        const u32 Kd0 = prmt(Kp, 0x1010u);   // (K0, K0)
        const u32 Kd1 = prmt(Kp, 0x3232u);   // (K1, K1)

        // dot' chains: 11 half2 terms per pixel, split 6+5
        u32 dp0a = hmul2u(cv0.x, yc0[0]);
        u32 dp1a = hmul2u(cv0.x, yc1[0]);
        u32 dp0b = hmul2u(cv1.z, yc0[6]);
        u32 dp1b = hmul2u(cv1.z, yc1[6]);
        dp0a = hfma2u(cv0.y, yc0[1], dp0a);  dp1a = hfma2u(cv0.y, yc1[1], dp1a);
        dp0b = hfma2u(cv1.w, yc0[7], dp0b);  dp1b = hfma2u(cv1.w, yc1[7], dp1b);
        dp0a = hfma2u(cv0.z, yc0[2], dp0a);  dp1a = hfma2u(cv0.z, yc1[2], dp1a);
        dp0b = hfma2u(cv2.x, yc0[8], dp0b);  dp1b = hfma2u(cv2.x, yc1[8], dp1b);
        dp0a = hfma2u(cv0.w, yc0[3], dp0a);  dp1a = hfma2u(cv0.w, yc1[3], dp1a);
        dp0b = hfma2u(cv2.y, yc0[9], dp0b);  dp1b = hfma2u(cv2.y, yc1[9], dp1b);
        dp0a = hfma2u(cv1.x, yc0[4], dp0a);  dp1a = hfma2u(cv1.x, yc1[4], dp1a);
        dp0b = hfma2u(cv2.z, yc0[10], dp0b); dp1b = hfma2u(cv2.z, yc1[10], dp1b);
        dp0a = hfma2u(cv1.y, yc0[5], dp0a);  dp1a = hfma2u(cv1.y, yc1[5], dp1a);
        const u32 dp0 = hadd2u(dp0a, dp0b);
        const u32 dp1 = hadd2u(dp1a, dp1b);

        accP0 = hfma2u(Kd0, dp0, accP0);
        accP1 = hfma2u(Kd1, dp1, accP1);
    }

    // ---- epilogue: part = -sum(K*dot') + true-OOB closed form ----
    float acc2;
    {
        __half2 a = *(__half2*)&accP0;
        __half2 b = *(__half2*)&accP1;
        acc2 = (__low2float(a) + __high2float(a)) + (__low2float(b) + __high2float(b));
    }
    float acc1 = 0.0f;
    if (g == 0) {
        const int h = th0 + py;
        const int rv = min(5, 127 - h) + min(5, h) + 1;
        #pragma unroll
        for (int pc = 0; pc < 2; ++pc) {
            const int w = tw0 + 2 * px + pc;
            const int cv = min(5, 127 - w) + min(5, w) + 1;
            const int noob = 121 - rv * cv;
            if (noob > 0) {
                const float4 xc = pc ? xc1 : xc0;
                const float sxs = xc.x * xc.x + xc.y * xc.y + xc.z * xc.z;  // scaled
                const float F = fmaf(0.9f, ex2(-sxs), 0.1f);
                acc1 += (float)noob * ex2((float)(h * h + w * w) * CXY) * F;
            }
        }
    }

    // ---- block reduction + fused final reduction (deterministic) ----
    float part = acc1 - acc2;
    #pragma unroll
    for (int o = 16; o > 0; o >>= 1) part += __shfl_xor_sync(0xffffffffu, part, o);
    const int warp = tid >> 5, lane = tid & 31;
    if (lane == 0) red[warp] = part;
    __syncthreads();
    const int bid = ((bz * gridDim.y) + blockIdx.y) * gridDim.x + blockIdx.x;
    if (tid == 0) {
        g_part[bid] = (red[0] + red[1]) + (red[2] + red[3]);
        __threadfence();
        unsigned old = atomicAdd(&g_cnt, 1u);
        lastflag = (old == NBLK - 1) ? 1 : 0;
    }
    __syncthreads();
    if (lastflag) {
        float v = (g_part[tid] + g_part[tid + 128]) +
                  (g_part[tid + 256] + g_part[tid + 384]);
        #pragma unroll
        for (int o = 16; o > 0; o >>= 1) v += __shfl_xor_sync(0xffffffffu, v, o);
        if (lane == 0) red[warp] = v;
        __syncthreads();
        if (tid == 0) {
            out[0] = ((red[0] + red[1]) + (red[2] + red[3])) * (1.0f / 65536.0f);
            g_cnt = 0;
        }
    }
}

extern "C" void kernel_launch(void* const* d_in, const int* in_sizes, int n_in,
                              void* d_out, int out_size) {
    const float* x = (const float*)d_in[0];
    const float* y = (const float*)d_in[1];
    (void)in_sizes; (void)n_in; (void)out_size;
    dim3 grid(WW / TW, HH / TH, 4);
    crf_fused<<<grid, NT>>>(x, y, (float*)d_out);
}